// round 1
// baseline (speedup 1.0000x reference)
#include <cuda_runtime.h>
#include <cuda_bf16.h>

// Dims
#define NB 32
#define NS 512
#define NE 1024
#define NP 256
#define NH 8
#define NHS 4096      /* NH*NS */
#define NM 16384      /* NB*NS */
#define NKC 768       /* NP*3 conv reduction */

// Scratch (allowed: __device__ globals)
__device__ __align__(16) float g_proj[(size_t)NM * NP];       // 16 MB
__device__ __align__(16) float g_rc[(size_t)NM * NP];         // 16 MB  rep_conv [b,s,p]
__device__ __align__(16) float g_Ex[(size_t)NM * NHS];        // 268 MB exp(logits)
__device__ __align__(16) float g_Z[NM];                       // row sums
__device__ __align__(16) float g_wnum[NB * NS];               // softmax-weight numerator
__device__ __align__(16) float g_Wc[NKC * NP];                // transposed conv_w
__device__ __align__(16) float g_base[NS];                    // masked-row analytic contribution

// ---------------------------------------------------------------- utilities
__global__ void k_zero() {
    int i = blockIdx.x * blockDim.x + threadIdx.x;
    if (i < NM) g_Z[i] = 0.f;
    if (i < NB * NS) g_wnum[i] = 0.f;
}

// g_Wc[kk][o] = conv_w[o][i][k],  kk = k*256 + i
__global__ void k_tw(const float* __restrict__ conv_w) {
    int kk = blockIdx.x;
    int o  = threadIdx.x;
    int i = kk & 255, k = kk >> 8;
    g_Wc[kk * NP + o] = conv_w[o * NKC + i * 3 + k];
}

// base[q] = sum_h softmax(attn_b)[h*S+q]  (contribution of a fully-masked row)
__global__ void k_base(const float* __restrict__ ab) {
    __shared__ float red[512];
    int t = threadIdx.x;
    float mx = -1e30f;
    for (int j = t; j < NHS; j += 512) mx = fmaxf(mx, ab[j]);
    red[t] = mx; __syncthreads();
    for (int s = 256; s; s >>= 1) { if (t < s) red[t] = fmaxf(red[t], red[t + s]); __syncthreads(); }
    mx = red[0]; __syncthreads();
    float sum = 0.f;
    for (int j = t; j < NHS; j += 512) sum += __expf(ab[j] - mx);
    red[t] = sum; __syncthreads();
    for (int s = 256; s; s >>= 1) { if (t < s) red[t] += red[t + s]; __syncthreads(); }
    float z0 = red[0];
    float acc = 0.f;
    for (int h = 0; h < NH; h++) acc += __expf(ab[h * NS + t] - mx);
    g_base[t] = acc / z0;
}

// ---------------------------------------------------------------- SGEMM cores
// Tile: 64(M) x 128(N) x 16(K), 256 threads, 4x8 per-thread.

// proj = x @ proj_w + proj_b      [16384,1024]x[1024,256]
__global__ void __launch_bounds__(256) k_proj(const float* __restrict__ X,
                                              const float* __restrict__ W,
                                              const float* __restrict__ bias) {
    __shared__ float As[16][68];
    __shared__ float Bs[16][128];
    const int m0 = blockIdx.x * 64;
    const int n0 = blockIdx.y * 128;
    const int tid = threadIdx.x;
    const int tx = tid & 15, ty = tid >> 4;
    const int aRow = tid >> 2, aK = (tid & 3) * 4;
    const int bK = tid >> 5, bN = (tid & 31) * 4;
    float acc[4][8];
#pragma unroll
    for (int i = 0; i < 4; i++)
#pragma unroll
        for (int j = 0; j < 8; j++) acc[i][j] = 0.f;

    for (int k0 = 0; k0 < NE; k0 += 16) {
        float4 av = *(const float4*)&X[(size_t)(m0 + aRow) * NE + k0 + aK];
        As[aK + 0][aRow] = av.x; As[aK + 1][aRow] = av.y;
        As[aK + 2][aRow] = av.z; As[aK + 3][aRow] = av.w;
        *(float4*)&Bs[bK][bN]     = *(const float4*)&W[(size_t)(k0 + bK) * NP + n0 + bN];
        *(float4*)&Bs[bK + 8][bN] = *(const float4*)&W[(size_t)(k0 + bK + 8) * NP + n0 + bN];
        __syncthreads();
#pragma unroll
        for (int kk = 0; kk < 16; kk++) {
            float a[4], bb[8];
            *(float4*)a        = *(const float4*)&As[kk][ty * 4];
            *(float4*)&bb[0]   = *(const float4*)&Bs[kk][tx * 8];
            *(float4*)&bb[4]   = *(const float4*)&Bs[kk][tx * 8 + 4];
#pragma unroll
            for (int i = 0; i < 4; i++)
#pragma unroll
                for (int j = 0; j < 8; j++) acc[i][j] += a[i] * bb[j];
        }
        __syncthreads();
    }
#pragma unroll
    for (int i = 0; i < 4; i++) {
        int row = m0 + ty * 4 + i;
#pragma unroll
        for (int j = 0; j < 8; j++)
            g_proj[(size_t)row * NP + n0 + tx * 8 + j] = acc[i][j] + bias[n0 + tx * 8 + j];
    }
}

// rep_conv[b,s,o] = mask * relu( sum_{k,i} proj[b,s+k,i] * conv_w[o,i,k] + conv_b[o] )
__global__ void __launch_bounds__(256) k_conv(const int* __restrict__ seqlen,
                                              const float* __restrict__ cbias) {
    const int b = blockIdx.z;
    const int l = seqlen[b];
    const int s0 = blockIdx.x * 64;
    if (s0 >= l - 1) return;                       // fully masked tile
    __shared__ float As[16][68];
    __shared__ float Bs[16][128];
    const int n0 = blockIdx.y * 128;
    const int tid = threadIdx.x;
    const int tx = tid & 15, ty = tid >> 4;
    const int aRow = tid >> 2, aK = (tid & 3) * 4;
    const int bK = tid >> 5, bN = (tid & 31) * 4;
    float acc[4][8];
#pragma unroll
    for (int i = 0; i < 4; i++)
#pragma unroll
        for (int j = 0; j < 8; j++) acc[i][j] = 0.f;

    for (int k0 = 0; k0 < NKC; k0 += 16) {
        int kc = k0 >> 8;                          // conv tap (constant per 16-chunk)
        int i0 = (k0 & 255) + aK;
        int srow = s0 + aRow + kc;
        float4 av = make_float4(0.f, 0.f, 0.f, 0.f);
        if (srow < NS) av = *(const float4*)&g_proj[(size_t)(b * NS + srow) * NP + i0];
        As[aK + 0][aRow] = av.x; As[aK + 1][aRow] = av.y;
        As[aK + 2][aRow] = av.z; As[aK + 3][aRow] = av.w;
        *(float4*)&Bs[bK][bN]     = *(const float4*)&g_Wc[(size_t)(k0 + bK) * NP + n0 + bN];
        *(float4*)&Bs[bK + 8][bN] = *(const float4*)&g_Wc[(size_t)(k0 + bK + 8) * NP + n0 + bN];
        __syncthreads();
#pragma unroll
        for (int kk = 0; kk < 16; kk++) {
            float a[4], bb[8];
            *(float4*)a      = *(const float4*)&As[kk][ty * 4];
            *(float4*)&bb[0] = *(const float4*)&Bs[kk][tx * 8];
            *(float4*)&bb[4] = *(const float4*)&Bs[kk][tx * 8 + 4];
#pragma unroll
            for (int i = 0; i < 4; i++)
#pragma unroll
                for (int j = 0; j < 8; j++) acc[i][j] += a[i] * bb[j];
        }
        __syncthreads();
    }
#pragma unroll
    for (int i = 0; i < 4; i++) {
        int s = s0 + ty * 4 + i;
        bool valid = (s >= 1) && (s < l - 1);
#pragma unroll
        for (int j = 0; j < 8; j++) {
            int col = n0 + tx * 8 + j;
            float v = fmaxf(acc[i][j] + cbias[col], 0.f);
            g_rc[(size_t)(b * NS + s) * NP + col] = valid ? v : 0.f;
        }
    }
}

// E = exp(rep_conv @ attn_w + attn_b); Z[row] += partial rowsum
__global__ void __launch_bounds__(256) k_logits(const int* __restrict__ seqlen,
                                                const float* __restrict__ AW,
                                                const float* __restrict__ ab) {
    const int b = blockIdx.z;
    const int l = seqlen[b];
    const int s0 = blockIdx.x * 64;
    if (s0 >= l - 1) return;
    __shared__ float As[16][68];
    __shared__ float Bs[16][128];
    __shared__ float Zs[64];
    const int n0 = blockIdx.y * 128;
    const int tid = threadIdx.x;
    const int tx = tid & 15, ty = tid >> 4;
    const int aRow = tid >> 2, aK = (tid & 3) * 4;
    const int bK = tid >> 5, bN = (tid & 31) * 4;
    if (tid < 64) Zs[tid] = 0.f;
    float acc[4][8];
#pragma unroll
    for (int i = 0; i < 4; i++)
#pragma unroll
        for (int j = 0; j < 8; j++) acc[i][j] = 0.f;

    for (int k0 = 0; k0 < NP; k0 += 16) {
        float4 av = *(const float4*)&g_rc[(size_t)(b * NS + s0 + aRow) * NP + k0 + aK];
        As[aK + 0][aRow] = av.x; As[aK + 1][aRow] = av.y;
        As[aK + 2][aRow] = av.z; As[aK + 3][aRow] = av.w;
        *(float4*)&Bs[bK][bN]     = *(const float4*)&AW[(size_t)(k0 + bK) * NHS + n0 + bN];
        *(float4*)&Bs[bK + 8][bN] = *(const float4*)&AW[(size_t)(k0 + bK + 8) * NHS + n0 + bN];
        __syncthreads();
#pragma unroll
        for (int kk = 0; kk < 16; kk++) {
            float a[4], bb[8];
            *(float4*)a      = *(const float4*)&As[kk][ty * 4];
            *(float4*)&bb[0] = *(const float4*)&Bs[kk][tx * 8];
            *(float4*)&bb[4] = *(const float4*)&Bs[kk][tx * 8 + 4];
#pragma unroll
            for (int i = 0; i < 4; i++)
#pragma unroll
                for (int j = 0; j < 8; j++) acc[i][j] += a[i] * bb[j];
        }
        __syncthreads();
    }
    // Epilogue: E = exp(logit), per-row partial sums
    float rs[4];
#pragma unroll
    for (int i = 0; i < 4; i++) {
        int s = s0 + ty * 4 + i;
        size_t base = (size_t)(b * NS + s) * NHS + n0 + tx * 8;
        float ev[8];
        rs[i] = 0.f;
#pragma unroll
        for (int j = 0; j < 8; j++) {
            ev[j] = __expf(acc[i][j] + ab[n0 + tx * 8 + j]);
            rs[i] += ev[j];
        }
        *(float4*)&g_Ex[base]     = make_float4(ev[0], ev[1], ev[2], ev[3]);
        *(float4*)&g_Ex[base + 4] = make_float4(ev[4], ev[5], ev[6], ev[7]);
    }
#pragma unroll
    for (int i = 0; i < 4; i++) atomicAdd(&Zs[ty * 4 + i], rs[i]);
    __syncthreads();
    if (tid < 64) atomicAdd(&g_Z[b * NS + s0 + tid], Zs[tid]);
}

// w numerator: wnum[b,q] += sum over processed rows s of (sum_h E[b,s,h*S+q]) / Z[b,s]
__global__ void __launch_bounds__(512) k_w(const int* __restrict__ seqlen) {
    const int b = blockIdx.y;
    const int l = seqlen[b];
    const int s0 = blockIdx.x * 64;
    if (s0 >= l - 1) return;
    const int q = threadIdx.x;
    float acc = 0.f;
    for (int s = s0; s < s0 + 64; s++) {
        size_t base = (size_t)(b * NS + s) * NHS;
        float sum = 0.f;
#pragma unroll
        for (int h = 0; h < NH; h++) sum += g_Ex[base + h * NS + q];
        acc += sum / g_Z[b * NS + s];
    }
    atomicAdd(&g_wnum[b * NS + q], acc);
}

// Finalize: w, rep_attn, classifier, softmax, argmax -> out
__global__ void __launch_bounds__(256) k_ra(const int* __restrict__ seqlen,
                                            const float* __restrict__ c1w,
                                            const float* __restrict__ c1b,
                                            const float* __restrict__ c2w,
                                            const float* __restrict__ c2b,
                                            float* __restrict__ out, int out_size) {
    __shared__ float w_sh[NS];
    __shared__ float ra[NP];
    __shared__ float h_sh[128];
    __shared__ float cls[2];
    const int b = blockIdx.x;
    const int t = threadIdx.x;
    const int l = seqlen[b];
    int pe = ((l - 1 + 63) / 64) * 64;            // processed row count
    if (pe > NS) pe = NS;
    float nmask = (float)(NS - pe);
    for (int q = t; q < NS; q += 256)
        w_sh[q] = (g_wnum[b * NS + q] + nmask * g_base[q]) * (1.0f / NH);
    __syncthreads();

    float acc = 0.f;
    for (int q = 1; q < l - 1; q++)               // rep_conv==0 (or garbage) outside
        acc += w_sh[q] * g_rc[(size_t)(b * NS + q) * NP + t];
    ra[t] = acc;
    __syncthreads();

    if (t < 128) {
        float hv = c1b[t];
        for (int p = 0; p < NP; p++) hv += ra[p] * c1w[p * 128 + t];
        h_sh[t] = hv > 0.f ? hv : 0.01f * hv;
    }
    __syncthreads();
    if (t < 2) {
        float cv = c2b[t];
        for (int j = 0; j < 128; j++) cv += h_sh[j] * c2w[j * 2 + t];
        cls[t] = cv;
    }
    __syncthreads();
    if (t == 0) {
        float m  = fmaxf(cls[0], cls[1]);
        float e0 = __expf(cls[0] - m), e1 = __expf(cls[1] - m);
        float inv = 1.f / (e0 + e1);
        float p0 = e0 * inv, p1 = e1 * inv;
        out[2 * b]     = p0;
        out[2 * b + 1] = p1;
        if (out_size >= 2 * NB + NB)
            out[2 * NB + b] = (p1 > p0) ? 1.0f : 0.0f;   // argmax, first-max tiebreak
    }
}

// ---------------------------------------------------------------- launch
extern "C" void kernel_launch(void* const* d_in, const int* in_sizes, int n_in,
                              void* d_out, int out_size) {
    const float* x      = (const float*)d_in[0];
    const int*   seqlen = (const int*)  d_in[1];
    const float* proj_w = (const float*)d_in[2];
    const float* proj_b = (const float*)d_in[3];
    const float* conv_w = (const float*)d_in[4];
    const float* conv_b = (const float*)d_in[5];
    const float* attn_w = (const float*)d_in[6];
    const float* attn_b = (const float*)d_in[7];
    const float* c1_w   = (const float*)d_in[8];
    const float* c1_b   = (const float*)d_in[9];
    const float* c2_w   = (const float*)d_in[10];
    const float* c2_b   = (const float*)d_in[11];
    float* out = (float*)d_out;

    k_zero  <<<32, 512>>>();
    k_tw    <<<NKC, NP>>>(conv_w);
    k_base  <<<1, 512>>>(attn_b);
    k_proj  <<<dim3(NM / 64, NP / 128), 256>>>(x, proj_w, proj_b);
    k_conv  <<<dim3(NS / 64, NP / 128, NB), 256>>>(seqlen, conv_b);
    k_logits<<<dim3(NS / 64, NHS / 128, NB), 256>>>(seqlen, attn_w, attn_b);
    k_w     <<<dim3(NS / 64, NB), 512>>>(seqlen);
    k_ra    <<<NB, 256>>>(seqlen, c1_w, c1_b, c2_w, c2_b, out, out_size);
}

// round 2
// speedup vs baseline: 1.3123x; 1.3123x over previous
#include <cuda_runtime.h>
#include <cuda_bf16.h>

// Dims
#define NB 32
#define NS 512
#define NE 1024
#define NP 256
#define NH 8
#define NHS 4096      /* NH*NS */
#define NM 16384      /* NB*NS */
#define NKC 768       /* NP*3 conv reduction */

// Scratch (allowed: __device__ globals)
__device__ __align__(16) float g_proj[(size_t)NM * NP];       // 16 MB
__device__ __align__(16) float g_rc[(size_t)NM * NP];         // 16 MB  rep_conv [b,s,p]
__device__ __align__(16) float g_Ex[(size_t)NM * NHS];        // 268 MB exp(logits)
__device__ __align__(16) float g_Z[NM];                       // row sums
__device__ __align__(16) float g_wnum[NB * NS];               // softmax-weight numerator
__device__ __align__(16) float g_Wc[NKC * NP];                // transposed conv_w
__device__ __align__(16) float g_base[NS];                    // masked-row analytic contribution

// ---------------------------------------------------------------- utilities
__global__ void k_zero() {
    int i = blockIdx.x * blockDim.x + threadIdx.x;
    if (i < NM) g_Z[i] = 0.f;
    if (i < NB * NS) g_wnum[i] = 0.f;
}

// g_Wc[kk][o] = conv_w[o][i][k],  kk = k*256 + i
__global__ void k_tw(const float* __restrict__ conv_w) {
    int kk = blockIdx.x;
    int o  = threadIdx.x;
    int i = kk & 255, k = kk >> 8;
    g_Wc[kk * NP + o] = conv_w[o * NKC + i * 3 + k];
}

// base[q] = sum_h softmax(attn_b)[h*S+q]  (contribution of a fully-masked row)
__global__ void k_base(const float* __restrict__ ab) {
    __shared__ float red[512];
    int t = threadIdx.x;
    float mx = -1e30f;
    for (int j = t; j < NHS; j += 512) mx = fmaxf(mx, ab[j]);
    red[t] = mx; __syncthreads();
    for (int s = 256; s; s >>= 1) { if (t < s) red[t] = fmaxf(red[t], red[t + s]); __syncthreads(); }
    mx = red[0]; __syncthreads();
    float sum = 0.f;
    for (int j = t; j < NHS; j += 512) sum += __expf(ab[j] - mx);
    red[t] = sum; __syncthreads();
    for (int s = 256; s; s >>= 1) { if (t < s) red[t] += red[t + s]; __syncthreads(); }
    float z0 = red[0];
    float acc = 0.f;
    for (int h = 0; h < NH; h++) acc += __expf(ab[h * NS + t] - mx);
    g_base[t] = acc / z0;
}

// ---------------------------------------------------------------- SGEMM cores
// 128x128x8 tile, 256 threads, 8x8 per-thread microtile, double-buffered smem.

#define SG_DECL                                                   \
    __shared__ float As[2][8][132];                               \
    __shared__ float Bs[2][8][128];                               \
    const int tid = threadIdx.x;                                  \
    const int tx = tid & 15, ty = tid >> 4;                       \
    const int aRow = tid >> 1, aCol = (tid & 1) * 4;              \
    const int bRow = tid >> 5, bCol = (tid & 31) * 4;             \
    float acc[8][8];                                              \
    _Pragma("unroll") for (int i = 0; i < 8; i++)                 \
    _Pragma("unroll") for (int j = 0; j < 8; j++) acc[i][j] = 0.f;

#define SG_STORE_A(buf, av)                                       \
    As[buf][aCol + 0][aRow] = av.x; As[buf][aCol + 1][aRow] = av.y; \
    As[buf][aCol + 2][aRow] = av.z; As[buf][aCol + 3][aRow] = av.w;

#define SG_COMPUTE(buf)                                           \
    _Pragma("unroll")                                             \
    for (int kk = 0; kk < 8; kk++) {                              \
        float afr[8], bfr[8];                                     \
        *(float4*)&afr[0] = *(const float4*)&As[buf][kk][ty * 8];     \
        *(float4*)&afr[4] = *(const float4*)&As[buf][kk][ty * 8 + 4]; \
        *(float4*)&bfr[0] = *(const float4*)&Bs[buf][kk][tx * 8];     \
        *(float4*)&bfr[4] = *(const float4*)&Bs[buf][kk][tx * 8 + 4]; \
        _Pragma("unroll") for (int i = 0; i < 8; i++)             \
        _Pragma("unroll") for (int j = 0; j < 8; j++)             \
            acc[i][j] += afr[i] * bfr[j];                         \
    }

// proj = x @ proj_w + proj_b      [16384,1024]x[1024,256]
__global__ void __launch_bounds__(256, 2) k_proj(const float* __restrict__ X,
                                                 const float* __restrict__ W,
                                                 const float* __restrict__ bias) {
    SG_DECL
    const int m0 = blockIdx.x * 128;
    const int n0 = blockIdx.y * 128;
    {
        float4 av = *(const float4*)&X[(size_t)(m0 + aRow) * NE + aCol];
        float4 bv = *(const float4*)&W[(size_t)bRow * NP + n0 + bCol];
        SG_STORE_A(0, av)
        *(float4*)&Bs[0][bRow][bCol] = bv;
    }
    __syncthreads();
    const int KT = NE / 8;
    for (int kt = 0; kt < KT; kt++) {
        const int buf = kt & 1;
        float4 an, bn;
        if (kt + 1 < KT) {
            int k0 = (kt + 1) * 8;
            an = *(const float4*)&X[(size_t)(m0 + aRow) * NE + k0 + aCol];
            bn = *(const float4*)&W[(size_t)(k0 + bRow) * NP + n0 + bCol];
        }
        SG_COMPUTE(buf)
        if (kt + 1 < KT) {
            SG_STORE_A(buf ^ 1, an)
            *(float4*)&Bs[buf ^ 1][bRow][bCol] = bn;
        }
        __syncthreads();
    }
#pragma unroll
    for (int i = 0; i < 8; i++) {
        int row = m0 + ty * 8 + i;
#pragma unroll
        for (int j = 0; j < 8; j++)
            g_proj[(size_t)row * NP + n0 + tx * 8 + j] = acc[i][j] + bias[n0 + tx * 8 + j];
    }
}

// rep_conv[b,s,o] = mask * relu( sum_{k,i} proj[b,s+k,i] * conv_w[o,i,k] + conv_b[o] )
__global__ void __launch_bounds__(256, 2) k_conv(const int* __restrict__ seqlen,
                                                 const float* __restrict__ cbias) {
    const int b = blockIdx.z;
    const int l = seqlen[b];
    const int s0 = blockIdx.x * 128;
    if (s0 >= l - 1) return;                       // fully masked tile
    SG_DECL
    const int n0 = blockIdx.y * 128;
    {
        int srow = s0 + aRow;                      // tap 0
        float4 av = *(const float4*)&g_proj[(size_t)(b * NS + srow) * NP + aCol];
        float4 bv = *(const float4*)&g_Wc[(size_t)bRow * NP + n0 + bCol];
        SG_STORE_A(0, av)
        *(float4*)&Bs[0][bRow][bCol] = bv;
    }
    __syncthreads();
    const int KT = NKC / 8;
    for (int kt = 0; kt < KT; kt++) {
        const int buf = kt & 1;
        float4 an, bn;
        if (kt + 1 < KT) {
            int k0 = (kt + 1) * 8;
            int tap = k0 >> 8;
            int i0 = (k0 & 255) + aCol;
            int srow = s0 + aRow + tap;
            an = make_float4(0.f, 0.f, 0.f, 0.f);
            if (srow < NS)
                an = *(const float4*)&g_proj[(size_t)(b * NS + srow) * NP + i0];
            bn = *(const float4*)&g_Wc[(size_t)(k0 + bRow) * NP + n0 + bCol];
        }
        SG_COMPUTE(buf)
        if (kt + 1 < KT) {
            SG_STORE_A(buf ^ 1, an)
            *(float4*)&Bs[buf ^ 1][bRow][bCol] = bn;
        }
        __syncthreads();
    }
#pragma unroll
    for (int i = 0; i < 8; i++) {
        int s = s0 + ty * 8 + i;
        bool valid = (s >= 1) && (s < l - 1);
#pragma unroll
        for (int j = 0; j < 8; j++) {
            int col = n0 + tx * 8 + j;
            float v = fmaxf(acc[i][j] + cbias[col], 0.f);
            g_rc[(size_t)(b * NS + s) * NP + col] = valid ? v : 0.f;
        }
    }
}

// E = exp(rep_conv @ attn_w + attn_b); Z[row] += partial rowsum
__global__ void __launch_bounds__(256, 2) k_logits(const int* __restrict__ seqlen,
                                                   const float* __restrict__ AW,
                                                   const float* __restrict__ ab) {
    const int b = blockIdx.z;
    const int l = seqlen[b];
    const int s0 = blockIdx.x * 128;
    if (s0 >= l - 1) return;
    SG_DECL
    __shared__ float Zs[128];
    const int n0 = blockIdx.y * 128;
    if (tid < 128) Zs[tid] = 0.f;
    {
        float4 av = *(const float4*)&g_rc[(size_t)(b * NS + s0 + aRow) * NP + aCol];
        float4 bv = *(const float4*)&AW[(size_t)bRow * NHS + n0 + bCol];
        SG_STORE_A(0, av)
        *(float4*)&Bs[0][bRow][bCol] = bv;
    }
    __syncthreads();
    const int KT = NP / 8;
    for (int kt = 0; kt < KT; kt++) {
        const int buf = kt & 1;
        float4 an, bn;
        if (kt + 1 < KT) {
            int k0 = (kt + 1) * 8;
            an = *(const float4*)&g_rc[(size_t)(b * NS + s0 + aRow) * NP + k0 + aCol];
            bn = *(const float4*)&AW[(size_t)(k0 + bRow) * NHS + n0 + bCol];
        }
        SG_COMPUTE(buf)
        if (kt + 1 < KT) {
            SG_STORE_A(buf ^ 1, an)
            *(float4*)&Bs[buf ^ 1][bRow][bCol] = bn;
        }
        __syncthreads();
    }
    // Epilogue: E = exp(logit), per-row partial sums
    float abl[8];
#pragma unroll
    for (int j = 0; j < 8; j++) abl[j] = ab[n0 + tx * 8 + j];
#pragma unroll
    for (int i = 0; i < 8; i++) {
        int s = s0 + ty * 8 + i;
        size_t base = (size_t)(b * NS + s) * NHS + n0 + tx * 8;
        float ev[8];
        float rs = 0.f;
#pragma unroll
        for (int j = 0; j < 8; j++) {
            ev[j] = __expf(acc[i][j] + abl[j]);
            rs += ev[j];
        }
        *(float4*)&g_Ex[base]     = make_float4(ev[0], ev[1], ev[2], ev[3]);
        *(float4*)&g_Ex[base + 4] = make_float4(ev[4], ev[5], ev[6], ev[7]);
        atomicAdd(&Zs[ty * 8 + i], rs);
    }
    __syncthreads();
    if (tid < 128) atomicAdd(&g_Z[b * NS + s0 + tid], Zs[tid]);
}

// w numerator: wnum[b,q] += sum over processed rows s of (sum_h E[b,s,h*S+q]) / Z[b,s]
__global__ void __launch_bounds__(512) k_w(const int* __restrict__ seqlen) {
    const int b = blockIdx.y;
    const int l = seqlen[b];
    const int s0 = blockIdx.x * 128;
    if (s0 >= l - 1) return;
    const int q = threadIdx.x;
    float acc = 0.f;
    for (int s = s0; s < s0 + 128; s++) {
        size_t base = (size_t)(b * NS + s) * NHS;
        float sum = 0.f;
#pragma unroll
        for (int h = 0; h < NH; h++) sum += g_Ex[base + h * NS + q];
        acc += sum / g_Z[b * NS + s];
    }
    atomicAdd(&g_wnum[b * NS + q], acc);
}

// Finalize: w, rep_attn, classifier, softmax, argmax -> out
__global__ void __launch_bounds__(256) k_ra(const int* __restrict__ seqlen,
                                            const float* __restrict__ c1w,
                                            const float* __restrict__ c1b,
                                            const float* __restrict__ c2w,
                                            const float* __restrict__ c2b,
                                            float* __restrict__ out, int out_size) {
    __shared__ float w_sh[NS];
    __shared__ float ra[NP];
    __shared__ float h_sh[128];
    __shared__ float cls[2];
    const int b = blockIdx.x;
    const int t = threadIdx.x;
    const int l = seqlen[b];
    int pe = ((l - 1 + 127) / 128) * 128;          // processed row count (tile=128)
    if (pe > NS) pe = NS;
    float nmask = (float)(NS - pe);
    for (int q = t; q < NS; q += 256)
        w_sh[q] = (g_wnum[b * NS + q] + nmask * g_base[q]) * (1.0f / NH);
    __syncthreads();

    float acc = 0.f;
    for (int q = 1; q < l - 1; q++)               // rep_conv==0 (or garbage) outside
        acc += w_sh[q] * g_rc[(size_t)(b * NS + q) * NP + t];
    ra[t] = acc;
    __syncthreads();

    if (t < 128) {
        float hv = c1b[t];
        for (int p = 0; p < NP; p++) hv += ra[p] * c1w[p * 128 + t];
        h_sh[t] = hv > 0.f ? hv : 0.01f * hv;
    }
    __syncthreads();
    if (t < 2) {
        float cv = c2b[t];
        for (int j = 0; j < 128; j++) cv += h_sh[j] * c2w[j * 2 + t];
        cls[t] = cv;
    }
    __syncthreads();
    if (t == 0) {
        float m  = fmaxf(cls[0], cls[1]);
        float e0 = __expf(cls[0] - m), e1 = __expf(cls[1] - m);
        float inv = 1.f / (e0 + e1);
        float p0 = e0 * inv, p1 = e1 * inv;
        out[2 * b]     = p0;
        out[2 * b + 1] = p1;
        if (out_size >= 2 * NB + NB)
            out[2 * NB + b] = (p1 > p0) ? 1.0f : 0.0f;   // argmax, first-max tiebreak
    }
}

// ---------------------------------------------------------------- launch
extern "C" void kernel_launch(void* const* d_in, const int* in_sizes, int n_in,
                              void* d_out, int out_size) {
    const float* x      = (const float*)d_in[0];
    const int*   seqlen = (const int*)  d_in[1];
    const float* proj_w = (const float*)d_in[2];
    const float* proj_b = (const float*)d_in[3];
    const float* conv_w = (const float*)d_in[4];
    const float* conv_b = (const float*)d_in[5];
    const float* attn_w = (const float*)d_in[6];
    const float* attn_b = (const float*)d_in[7];
    const float* c1_w   = (const float*)d_in[8];
    const float* c1_b   = (const float*)d_in[9];
    const float* c2_w   = (const float*)d_in[10];
    const float* c2_b   = (const float*)d_in[11];
    float* out = (float*)d_out;

    k_zero  <<<32, 512>>>();
    k_tw    <<<NKC, NP>>>(conv_w);
    k_base  <<<1, 512>>>(attn_b);
    k_proj  <<<dim3(NM / 128, NP / 128), 256>>>(x, proj_w, proj_b);
    k_conv  <<<dim3(NS / 128, NP / 128, NB), 256>>>(seqlen, conv_b);
    k_logits<<<dim3(NS / 128, NHS / 128, NB), 256>>>(seqlen, attn_w, attn_b);
    k_w     <<<dim3(NS / 128, NB), 512>>>(seqlen);
    k_ra    <<<NB, 256>>>(seqlen, c1_w, c1_b, c2_w, c2_b, out, out_size);
}